// round 13
// baseline (speedup 1.0000x reference)
#include <cuda_runtime.h>

// out = -weight * sum_{k=0}^{M-1} f[k]*f[k+D] / (N-1),  M = (N-1)*D, D=2000.
//
// R12 two-tier steal pool (32KB coarse chunks + 8KB fine tail chunks to kill
// the end-of-pool stagger) with __launch_bounds__(256, 6): pins regs<=42 so
// residency stays 6 blocks/SM (48 warps, 384 outstanding loads) instead of
// the 5 blocks/SM the 44-reg build fell to. Stacks the tail gain on the
// full-strength request stream.

#define NBLOCKS 1216
#define NTHREADS 256
#define CHUNK 2048            // coarse: float4 per chunk = 32KB
#define FINE 512              // fine:   float4 per chunk = 8KB

__device__ float g_partials[NBLOCKS];
__device__ unsigned int g_next = 0;
__device__ unsigned int g_done = 0;

__global__ __launch_bounds__(NTHREADS, 6)
void shifted_dot_2tier6(const float4* __restrict__ in4, long long Mv, int Dv,
                        int n_coarse, int nchunks, long long fine_base,
                        const float* __restrict__ weight, float* __restrict__ out,
                        float inv_nm1) {
    __shared__ unsigned int s_next[2];

    if (threadIdx.x == 0) s_next[0] = atomicAdd(&g_next, 1u);
    __syncthreads();
    int par = 0;
    unsigned int c = s_next[0];

    float acc = 0.0f;

    while (c < (unsigned int)nchunks) {
        // Prefetch next chunk id; latency hidden behind the streaming.
        if (threadIdx.x == 0) s_next[par ^ 1] = atomicAdd(&g_next, 1u);

        if (c < (unsigned int)n_coarse) {
            // coarse chunk: always full 2048 float4
            const long long beg = (long long)c * CHUNK;
            long long t = beg + threadIdx.x;
            #pragma unroll
            for (int g = 0; g < CHUNK / (4 * NTHREADS); g++) {
                float4 a0 = in4[t];
                float4 a1 = in4[t + NTHREADS];
                float4 a2 = in4[t + 2 * NTHREADS];
                float4 a3 = in4[t + 3 * NTHREADS];
                float4 b0 = in4[t + Dv];
                float4 b1 = in4[t + NTHREADS + Dv];
                float4 b2 = in4[t + 2 * NTHREADS + Dv];
                float4 b3 = in4[t + 3 * NTHREADS + Dv];
                acc += a0.x * b0.x + a0.y * b0.y + a0.z * b0.z + a0.w * b0.w;
                acc += a1.x * b1.x + a1.y * b1.y + a1.z * b1.z + a1.w * b1.w;
                acc += a2.x * b2.x + a2.y * b2.y + a2.z * b2.z + a2.w * b2.w;
                acc += a3.x * b3.x + a3.y * b3.y + a3.z * b3.z + a3.w * b3.w;
                t += 4 * NTHREADS;
            }
        } else {
            // fine chunk: 512 float4 (last one may be partial)
            const long long beg = fine_base
                + (long long)(c - (unsigned int)n_coarse) * FINE;
            long long end = beg + FINE;
            if (end > Mv) end = Mv;
            for (long long t = beg + threadIdx.x; t < end; t += NTHREADS) {
                float4 a = in4[t];
                float4 b = in4[t + Dv];
                acc += a.x * b.x + a.y * b.y + a.z * b.z + a.w * b.w;
            }
        }

        __syncthreads();        // id visibility only — no data drain
        par ^= 1;
        c = s_next[par];
    }

    // One block reduction at the very end.
    #pragma unroll
    for (int o = 16; o > 0; o >>= 1)
        acc += __shfl_xor_sync(0xffffffff, acc, o);

    __shared__ float s[NTHREADS / 32];
    if ((threadIdx.x & 31) == 0) s[threadIdx.x >> 5] = acc;
    __syncthreads();

    __shared__ bool is_last;
    if (threadIdx.x == 0) {
        float v = 0.0f;
        #pragma unroll
        for (int i = 0; i < NTHREADS / 32; i++) v += s[i];
        g_partials[blockIdx.x] = v;
        __threadfence();
        unsigned int old = atomicAdd(&g_done, 1u);
        is_last = (old == gridDim.x - 1);
    }
    __syncthreads();

    if (is_last) {
        const volatile float* p = g_partials;
        float v = 0.0f;
        for (int i = threadIdx.x; i < (int)gridDim.x; i += NTHREADS)
            v += p[i];
        #pragma unroll
        for (int o = 16; o > 0; o >>= 1)
            v += __shfl_xor_sync(0xffffffff, v, o);

        __shared__ float s2[NTHREADS / 32];
        if ((threadIdx.x & 31) == 0) s2[threadIdx.x >> 5] = v;
        __syncthreads();
        if (threadIdx.x == 0) {
            float tot = 0.0f;
            #pragma unroll
            for (int i = 0; i < NTHREADS / 32; i++) tot += s2[i];
            out[0] = -(*weight) * tot * inv_nm1;
            g_next = 0;   // reset for next graph replay
            g_done = 0;
        }
    }
}

extern "C" void kernel_launch(void* const* d_in, const int* in_sizes, int n_in,
                              void* d_out, int out_size) {
    const float* factor = (const float*)d_in[0];
    const float* weight = (const float*)d_in[1];
    float* out = (float*)d_out;

    const int D = 2000;
    const long long total = (long long)in_sizes[0];   // N * D
    const long long N = total / D;
    const long long M = (N - 1) * (long long)D;       // divisible by 4
    const long long Mv = M / 4;                       // float4 count
    const int Dv = D / 4;

    // fine region: ~4 fine chunks per block (~38MB, ~7% of data)
    const long long fine_target = (long long)4 * NBLOCKS * FINE;
    long long coarse_elems = Mv - fine_target;
    if (coarse_elems < 0) coarse_elems = 0;
    const int n_coarse = (int)(coarse_elems / CHUNK);
    const long long fine_base = (long long)n_coarse * CHUNK;
    const int n_fine = (int)((Mv - fine_base + FINE - 1) / FINE);
    const int nchunks = n_coarse + n_fine;

    shifted_dot_2tier6<<<NBLOCKS, NTHREADS>>>(
        (const float4*)factor, Mv, Dv, n_coarse, nchunks, fine_base,
        weight, out, 1.0f / (float)(N - 1));
}

// round 15
// speedup vs baseline: 1.0363x; 1.0363x over previous
#include <cuda_runtime.h>

// out = -weight * sum_{k=0}^{M-1} f[k]*f[k+D] / (N-1),  M = (N-1)*D, D=2000.
//
// R8 hot loop verbatim (persistent grid, dynamic 32KB-chunk stealing,
// per-thread register accumulators, ONE __syncthreads per chunk) followed by
// a SEPARATE fine-tail steal loop (8KB chunks, own counter) for the last ~7%
// of data, cutting the end-of-pool stagger from ~one 32KB chunk to ~8KB.
//
// DEADLOCK FIX vs previous round: a __syncthreads() between the coarse-loop
// exit and the fine-loop counter init. Without it, thread 0 could overwrite
// s_next[0] with a fine id before a slow thread read its coarse exit value,
// sending that thread back into the coarse loop -> divergent barriers.

#define NBLOCKS 1216
#define NTHREADS 256
#define CHUNK 2048            // coarse: float4 per chunk = 32KB
#define FINE 512              // fine:   float4 per chunk = 8KB

__device__ float g_partials[NBLOCKS];
__device__ unsigned int g_next = 0;      // coarse counter
__device__ unsigned int g_next_f = 0;    // fine counter
__device__ unsigned int g_done = 0;

__global__ __launch_bounds__(NTHREADS)
void shifted_dot_seq2(const float4* __restrict__ in4, long long Mv, int Dv,
                      int n_coarse, int n_fine, long long fine_base,
                      const float* __restrict__ weight, float* __restrict__ out,
                      float inv_nm1) {
    __shared__ unsigned int s_next[2];

    float acc = 0.0f;

    // ---------- coarse loop: identical structure to R8 ----------
    if (threadIdx.x == 0) s_next[0] = atomicAdd(&g_next, 1u);
    __syncthreads();
    int par = 0;
    unsigned int c = s_next[0];

    while (c < (unsigned int)n_coarse) {
        if (threadIdx.x == 0) s_next[par ^ 1] = atomicAdd(&g_next, 1u);

        const long long beg = (long long)c * CHUNK;
        const long long end = beg + CHUNK;   // coarse chunks always full

        long long t = beg + threadIdx.x;
        for (; t + 3 * NTHREADS < end; t += 4 * NTHREADS) {
            float4 a0 = in4[t];
            float4 a1 = in4[t + NTHREADS];
            float4 a2 = in4[t + 2 * NTHREADS];
            float4 a3 = in4[t + 3 * NTHREADS];
            float4 b0 = in4[t + Dv];
            float4 b1 = in4[t + NTHREADS + Dv];
            float4 b2 = in4[t + 2 * NTHREADS + Dv];
            float4 b3 = in4[t + 3 * NTHREADS + Dv];
            acc += a0.x * b0.x + a0.y * b0.y + a0.z * b0.z + a0.w * b0.w;
            acc += a1.x * b1.x + a1.y * b1.y + a1.z * b1.z + a1.w * b1.w;
            acc += a2.x * b2.x + a2.y * b2.y + a2.z * b2.z + a2.w * b2.w;
            acc += a3.x * b3.x + a3.y * b3.y + a3.z * b3.z + a3.w * b3.w;
        }
        for (; t < end; t += NTHREADS) {
            float4 a = in4[t];
            float4 b = in4[t + Dv];
            acc += a.x * b.x + a.y * b.y + a.z * b.z + a.w * b.w;
        }

        __syncthreads();        // id visibility only — no data drain
        par ^= 1;
        c = s_next[par];
    }

    __syncthreads();   // FIX: all threads done reading s_next before reuse

    // ---------- fine tail loop: 8KB chunks, separate counter ----------
    if (threadIdx.x == 0) s_next[0] = atomicAdd(&g_next_f, 1u);
    __syncthreads();
    par = 0;
    c = s_next[0];

    while (c < (unsigned int)n_fine) {
        if (threadIdx.x == 0) s_next[par ^ 1] = atomicAdd(&g_next_f, 1u);

        const long long beg = fine_base + (long long)c * FINE;
        long long end = beg + FINE;
        if (end > Mv) end = Mv;

        for (long long t = beg + threadIdx.x; t < end; t += NTHREADS) {
            float4 a = in4[t];
            float4 b = in4[t + Dv];
            acc += a.x * b.x + a.y * b.y + a.z * b.z + a.w * b.w;
        }

        __syncthreads();
        par ^= 1;
        c = s_next[par];
    }

    __syncthreads();   // symmetric guard before smem reuse in epilogue

    // ---------- one block reduction at the very end ----------
    #pragma unroll
    for (int o = 16; o > 0; o >>= 1)
        acc += __shfl_xor_sync(0xffffffff, acc, o);

    __shared__ float s[NTHREADS / 32];
    if ((threadIdx.x & 31) == 0) s[threadIdx.x >> 5] = acc;
    __syncthreads();

    __shared__ bool is_last;
    if (threadIdx.x == 0) {
        float v = 0.0f;
        #pragma unroll
        for (int i = 0; i < NTHREADS / 32; i++) v += s[i];
        g_partials[blockIdx.x] = v;
        __threadfence();
        unsigned int old = atomicAdd(&g_done, 1u);
        is_last = (old == gridDim.x - 1);
    }
    __syncthreads();

    if (is_last) {
        const volatile float* p = g_partials;
        float v = 0.0f;
        for (int i = threadIdx.x; i < (int)gridDim.x; i += NTHREADS)
            v += p[i];
        #pragma unroll
        for (int o = 16; o > 0; o >>= 1)
            v += __shfl_xor_sync(0xffffffff, v, o);

        __shared__ float s2[NTHREADS / 32];
        if ((threadIdx.x & 31) == 0) s2[threadIdx.x >> 5] = v;
        __syncthreads();
        if (threadIdx.x == 0) {
            float tot = 0.0f;
            #pragma unroll
            for (int i = 0; i < NTHREADS / 32; i++) tot += s2[i];
            out[0] = -(*weight) * tot * inv_nm1;
            g_next = 0;     // reset for next graph replay
            g_next_f = 0;
            g_done = 0;
        }
    }
}

extern "C" void kernel_launch(void* const* d_in, const int* in_sizes, int n_in,
                              void* d_out, int out_size) {
    const float* factor = (const float*)d_in[0];
    const float* weight = (const float*)d_in[1];
    float* out = (float*)d_out;

    const int D = 2000;
    const long long total = (long long)in_sizes[0];   // N * D
    const long long N = total / D;
    const long long M = (N - 1) * (long long)D;       // divisible by 4
    const long long Mv = M / 4;                       // float4 count
    const int Dv = D / 4;

    // fine region: ~4 fine chunks per block (~38MB, ~7% of data)
    const long long fine_target = (long long)4 * NBLOCKS * FINE;
    long long coarse_elems = Mv - fine_target;
    if (coarse_elems < 0) coarse_elems = 0;
    const int n_coarse = (int)(coarse_elems / CHUNK);
    const long long fine_base = (long long)n_coarse * CHUNK;
    const int n_fine = (int)((Mv - fine_base + FINE - 1) / FINE);

    shifted_dot_seq2<<<NBLOCKS, NTHREADS>>>(
        (const float4*)factor, Mv, Dv, n_coarse, n_fine, fine_base,
        weight, out, 1.0f / (float)(N - 1));
}

// round 17
// speedup vs baseline: 1.0608x; 1.0236x over previous
#include <cuda_runtime.h>

// out = -weight * sum_{k=0}^{M-1} f[k]*f[k+D] / (N-1),  M = (N-1)*D, D=2000.
//
// FINAL (= R8, session best: 82.4us bench / 82.9us ncu, DRAM 80.5%).
// Persistent grid + dynamic 32KB-chunk stealing. Per-thread register
// accumulator carried ACROSS chunks: no per-chunk smem reduce, no load-drain
// barrier, so chunk boundaries never empty the memory pipeline. Chunk-id
// handoff: thread0 atomic -> double-buffered smem slot -> one __syncthreads
// (id visibility only). Contiguous 32KB sweep keeps the +8KB b-stream
// L1-resident (L2 ~1x traffic). 1216 blocks -> 6 resident/SM at regs=40,
// 48 warps x 8 batched LDG.128 in flight = saturating request stream.
// Session evidence: 6 structural alternatives (TMA pipeline, L2 prefetch,
// forced occupancy, two-tier pools) all plateau at DRAM 80-81% => this is
// the pattern's HBM ceiling; this config sits ~3% above the traffic floor.

#define NBLOCKS 1216
#define NTHREADS 256
#define CHUNK 2048            // float4 per chunk = 32KB

__device__ float g_partials[NBLOCKS];
__device__ unsigned int g_next = 0;
__device__ unsigned int g_done = 0;

__global__ __launch_bounds__(NTHREADS)
void shifted_dot_dyn3(const float4* __restrict__ in4, long long Mv, int Dv,
                      int nchunks,
                      const float* __restrict__ weight, float* __restrict__ out,
                      float inv_nm1) {
    __shared__ unsigned int s_next[2];

    if (threadIdx.x == 0) s_next[0] = atomicAdd(&g_next, 1u);
    __syncthreads();
    int par = 0;
    unsigned int c = s_next[0];

    float acc = 0.0f;

    while (c < (unsigned int)nchunks) {
        // Prefetch next chunk id; hides atomic latency behind the streaming.
        if (threadIdx.x == 0) s_next[par ^ 1] = atomicAdd(&g_next, 1u);

        const long long beg = (long long)c * CHUNK;
        long long end = beg + CHUNK;
        if (end > Mv) end = Mv;

        long long t = beg + threadIdx.x;
        for (; t + 3 * NTHREADS < end; t += 4 * NTHREADS) {
            float4 a0 = in4[t];
            float4 a1 = in4[t + NTHREADS];
            float4 a2 = in4[t + 2 * NTHREADS];
            float4 a3 = in4[t + 3 * NTHREADS];
            float4 b0 = in4[t + Dv];
            float4 b1 = in4[t + NTHREADS + Dv];
            float4 b2 = in4[t + 2 * NTHREADS + Dv];
            float4 b3 = in4[t + 3 * NTHREADS + Dv];
            acc += a0.x * b0.x + a0.y * b0.y + a0.z * b0.z + a0.w * b0.w;
            acc += a1.x * b1.x + a1.y * b1.y + a1.z * b1.z + a1.w * b1.w;
            acc += a2.x * b2.x + a2.y * b2.y + a2.z * b2.z + a2.w * b2.w;
            acc += a3.x * b3.x + a3.y * b3.y + a3.z * b3.z + a3.w * b3.w;
        }
        for (; t < end; t += NTHREADS) {
            float4 a = in4[t];
            float4 b = in4[t + Dv];
            acc += a.x * b.x + a.y * b.y + a.z * b.z + a.w * b.w;
        }

        __syncthreads();        // id visibility only — no data drain
        par ^= 1;
        c = s_next[par];
    }

    // One block reduction at the very end.
    #pragma unroll
    for (int o = 16; o > 0; o >>= 1)
        acc += __shfl_xor_sync(0xffffffff, acc, o);

    __shared__ float s[NTHREADS / 32];
    if ((threadIdx.x & 31) == 0) s[threadIdx.x >> 5] = acc;
    __syncthreads();

    __shared__ bool is_last;
    if (threadIdx.x == 0) {
        float v = 0.0f;
        #pragma unroll
        for (int i = 0; i < NTHREADS / 32; i++) v += s[i];
        g_partials[blockIdx.x] = v;
        __threadfence();
        unsigned int old = atomicAdd(&g_done, 1u);
        is_last = (old == gridDim.x - 1);
    }
    __syncthreads();

    if (is_last) {
        const volatile float* p = g_partials;
        float v = 0.0f;
        for (int i = threadIdx.x; i < (int)gridDim.x; i += NTHREADS)
            v += p[i];
        #pragma unroll
        for (int o = 16; o > 0; o >>= 1)
            v += __shfl_xor_sync(0xffffffff, v, o);

        __shared__ float s2[NTHREADS / 32];
        if ((threadIdx.x & 31) == 0) s2[threadIdx.x >> 5] = v;
        __syncthreads();
        if (threadIdx.x == 0) {
            float tot = 0.0f;
            #pragma unroll
            for (int i = 0; i < NTHREADS / 32; i++) tot += s2[i];
            out[0] = -(*weight) * tot * inv_nm1;
            g_next = 0;   // reset for next graph replay
            g_done = 0;
        }
    }
}

extern "C" void kernel_launch(void* const* d_in, const int* in_sizes, int n_in,
                              void* d_out, int out_size) {
    const float* factor = (const float*)d_in[0];
    const float* weight = (const float*)d_in[1];
    float* out = (float*)d_out;

    const int D = 2000;
    const long long total = (long long)in_sizes[0];   // N * D
    const long long N = total / D;
    const long long M = (N - 1) * (long long)D;       // divisible by 4
    const long long Mv = M / 4;                       // float4 count
    const int Dv = D / 4;
    const int nchunks = (int)((Mv + CHUNK - 1) / CHUNK);

    shifted_dot_dyn3<<<NBLOCKS, NTHREADS>>>(
        (const float4*)factor, Mv, Dv, nchunks, weight, out,
        1.0f / (float)(N - 1));
}